// round 14
// baseline (speedup 1.0000x reference)
#include <cuda_runtime.h>
#include <cuda_bf16.h>
#include <math.h>

// ---------------------------------------------------------------------------
// SRNN ALIF — bit-exact-vs-XLA-CPU fp32 (round 14).
// Phase 1 fused: 96 pool-worker blocks (t-ascending, counter-flagged) +
// 800 GEMM1+2 tiles (by-ascending, spin on flags) + 256 transpose blocks,
// all in ONE launch -> pool DRAM time hidden under GEMM compute.
// GEMM math byte-identical to round 13 (serial ascending-k FFMA chains).
// ---------------------------------------------------------------------------

#define T_STEPS 100
#define NBATCH  64
#define HID     512
#define INSZ    1024

__device__ float d_xp  [2 * T_STEPS * NBATCH * INSZ];   // pooled [c][t][n][1024]
__device__ float d_in12[2 * T_STEPS * NBATCH * HID];    // ff proj [c][t][n][512]
__device__ float d_s12 [T_STEPS * NBATCH * INSZ];       // spikes s1||s2 [t][n][1024]
__device__ float d_ff3 [T_STEPS * NBATCH * HID];        // concat@W1 (+b1) [t][n][512]
__device__ float d_wt  [HID * HID];                     // w_h2h3 transposed [j][i]
__device__ int   d_cnt [2 * T_STEPS];                   // pool completion, idx t*2+c

// ---------------------------------------------------------------------------
// XLA:CPU exp — Cephes/Eigen pexp<float> with FMA, exact op order.
// ---------------------------------------------------------------------------
__device__ __forceinline__ float xla_expf(float x) {
    const float exp_hi = 88.723164f, exp_lo = -88.723164f;
    x = fminf(fmaxf(x, exp_lo), exp_hi);
    float m = floorf(__fmaf_rn(x, 1.44269504088896341f, 0.5f));
    float r = __fmaf_rn(m, -0.693359375f, x);
    r = __fmaf_rn(m, 2.12194440e-4f, r);
    float r2 = __fmul_rn(r, r);
    float y = 1.9875691500e-4f;
    y = __fmaf_rn(y, r, 1.3981999507e-3f);
    y = __fmaf_rn(y, r, 8.3334519073e-3f);
    y = __fmaf_rn(y, r, 4.1665795894e-2f);
    y = __fmaf_rn(y, r, 1.6666665459e-1f);
    y = __fmaf_rn(y, r, 5.0000001201e-1f);
    y = __fmaf_rn(y, r2, r);
    y = __fadd_rn(y, 1.0f);
    return ldexpf(y, (int)m);
}

__device__ __forceinline__ float alpha_of(float tau) {
    return xla_expf(__fdiv_rn(-1.0f, tau));
}

// ---------------------------------------------------------------------------
// pool source address for flat output index (layout [c][t][n][1024])
// ---------------------------------------------------------------------------
__device__ __forceinline__ const float* pool_src(int out, const float* x) {
    int i    = out & 1023;
    int n    = (out >> 10) & 63;
    int rest = out >> 16;          // c*100 + t
    int t    = rest % 100;
    int c    = rest / 100;
    int ph = i >> 5, pw = i & 31;
    return x + (((size_t)(n * 100 + t) * 2 + c) << 14) + ph * 512 + pw * 4;
}

// ---------------------------------------------------------------------------
// GEMM pieces (byte-identical math to round 13)
// ---------------------------------------------------------------------------
#define BM 128
#define BN 64
#define BK 16
#define NPOOLW 96
#define NGEMM12 800

__device__ __forceinline__ void gemm_compute_tile(
    const float As[BK][BM], const float Ws[BK][BN],
    int ty, int tx, float acc[8][4]) {
#pragma unroll
    for (int k = 0; k < BK; k++) {
        float a[8], w[4];
#pragma unroll
        for (int r = 0; r < 8; r++) a[r] = As[k][ty * 8 + r];
#pragma unroll
        for (int cI = 0; cI < 4; cI++) w[cI] = Ws[k][tx * 4 + cI];
#pragma unroll
        for (int r = 0; r < 8; r++)
#pragma unroll
            for (int cI = 0; cI < 4; cI++)
                acc[r][cI] = __fmaf_rn(a[r], w[cI], acc[r][cI]);
    }
}

// A loads via __ldcg (L2) — producer blocks wrote xp in this same launch.
__device__ __forceinline__ float4 ldcg4(const float* p) {
    return __ldcg((const float4*)p);
}

__device__ void gemm_body(const float* __restrict__ A, const float* __restrict__ W,
                          const float* __restrict__ bias_a, float* __restrict__ C,
                          int rowBase, int colBase, bool a_volatile) {
    __shared__ float As[2][BK][BM];
    __shared__ float Ws[2][BK][BN];
    int tid = threadIdx.x;
    int tx = tid & 15;
    int ty = tid >> 4;
    int mA0 = (tid * 2)     >> 2, kqA0 = (tid * 2)     & 3;
    int mA1 = (tid * 2 + 1) >> 2, kqA1 = (tid * 2 + 1) & 3;
    int nW  = tid >> 2,           kqW  = tid & 3;
    const float* Arow0 = A + (size_t)(rowBase + mA0) * 1024 + kqA0 * 4;
    const float* Arow1 = A + (size_t)(rowBase + mA1) * 1024 + kqA1 * 4;
    const float* Wrow  = W + (size_t)(colBase + nW)  * 1024 + kqW  * 4;

    float acc[8][4];
#pragma unroll
    for (int r = 0; r < 8; r++)
#pragma unroll
        for (int cI = 0; cI < 4; cI++) acc[r][cI] = 0.f;

    {
        float4 v0 = a_volatile ? ldcg4(Arow0) : *(const float4*)Arow0;
        float4 v1 = a_volatile ? ldcg4(Arow1) : *(const float4*)Arow1;
        float4 vw = *(const float4*)Wrow;
        As[0][kqA0 * 4 + 0][mA0] = v0.x; As[0][kqA0 * 4 + 1][mA0] = v0.y;
        As[0][kqA0 * 4 + 2][mA0] = v0.z; As[0][kqA0 * 4 + 3][mA0] = v0.w;
        As[0][kqA1 * 4 + 0][mA1] = v1.x; As[0][kqA1 * 4 + 1][mA1] = v1.y;
        As[0][kqA1 * 4 + 2][mA1] = v1.z; As[0][kqA1 * 4 + 3][mA1] = v1.w;
        Ws[0][kqW * 4 + 0][nW] = vw.x; Ws[0][kqW * 4 + 1][nW] = vw.y;
        Ws[0][kqW * 4 + 2][nW] = vw.z; Ws[0][kqW * 4 + 3][nW] = vw.w;
    }
    __syncthreads();

    for (int it = 0; it < 63; ++it) {
        int cur = it & 1, nb = 1 - cur;
        int koff = (it + 1) * BK;
        float4 v0 = a_volatile ? ldcg4(Arow0 + koff) : *(const float4*)(Arow0 + koff);
        float4 v1 = a_volatile ? ldcg4(Arow1 + koff) : *(const float4*)(Arow1 + koff);
        float4 vw = *(const float4*)(Wrow + koff);

        gemm_compute_tile(As[cur], Ws[cur], ty, tx, acc);

        As[nb][kqA0 * 4 + 0][mA0] = v0.x; As[nb][kqA0 * 4 + 1][mA0] = v0.y;
        As[nb][kqA0 * 4 + 2][mA0] = v0.z; As[nb][kqA0 * 4 + 3][mA0] = v0.w;
        As[nb][kqA1 * 4 + 0][mA1] = v1.x; As[nb][kqA1 * 4 + 1][mA1] = v1.y;
        As[nb][kqA1 * 4 + 2][mA1] = v1.z; As[nb][kqA1 * 4 + 3][mA1] = v1.w;
        Ws[nb][kqW * 4 + 0][nW] = vw.x; Ws[nb][kqW * 4 + 1][nW] = vw.y;
        Ws[nb][kqW * 4 + 2][nW] = vw.z; Ws[nb][kqW * 4 + 3][nW] = vw.w;
        __syncthreads();
    }
    gemm_compute_tile(As[1], Ws[1], ty, tx, acc);

    float badd[4];
#pragma unroll
    for (int cI = 0; cI < 4; cI++)
        badd[cI] = bias_a ? bias_a[colBase + tx * 4 + cI] : 0.f;
#pragma unroll
    for (int r = 0; r < 8; r++) {
        size_t rowOff = (size_t)(rowBase + ty * 8 + r) * 512 + colBase + tx * 4;
#pragma unroll
        for (int cI = 0; cI < 4; cI++)
            C[rowOff + cI] = __fadd_rn(acc[r][cI], badd[cI]);
    }
}

// ---------------------------------------------------------------------------
// Phase-1 fused kernel: pool workers + GEMM1+2 tiles + transpose.
// Grid: [0,96) pool workers; [96,896) gemm tiles (by-major); [896,1152) transpose.
// ---------------------------------------------------------------------------
__global__ __launch_bounds__(256, 3)
void fused1_kernel(const float* __restrict__ x, const float* __restrict__ wh2h3,
                   const float* __restrict__ w1, const float* __restrict__ b1,
                   const float* __restrict__ w2, const float* __restrict__ b2) {
    int b = blockIdx.x;
    int tid = threadIdx.x;

    if (b < NPOOLW) {
        // ---- pool worker: chunks in t-ascending order, flag per (t,c) ----
        for (int j = b; j < 25600; j += NPOOLW) {
            int t = j >> 8;                 // 256 chunks per t (128 per (t,c))
            int c = (j >> 7) & 1;
            int inner = j & 127;
            int out0 = ((c * 100 + t) << 16) + inner * 512 + tid;
            int out1 = out0 + 256;
            const float* s0 = pool_src(out0, x);
            const float* s1 = pool_src(out1, x);
            float4 v[8];
#pragma unroll
            for (int r = 0; r < 4; r++) {
                v[r]     = *(const float4*)(s0 + r * 128);
                v[r + 4] = *(const float4*)(s1 + r * 128);
            }
            float mx0 = -3.4e38f, mx1 = -3.4e38f;
#pragma unroll
            for (int r = 0; r < 4; r++) {
                mx0 = fmaxf(mx0, fmaxf(fmaxf(v[r].x, v[r].y), fmaxf(v[r].z, v[r].w)));
                mx1 = fmaxf(mx1, fmaxf(fmaxf(v[r+4].x, v[r+4].y), fmaxf(v[r+4].z, v[r+4].w)));
            }
            d_xp[out0] = mx0;
            d_xp[out1] = mx1;
            __threadfence();
            __syncthreads();
            if (tid == 0) atomicAdd(&d_cnt[t * 2 + c], 1);
        }
    } else if (b < NPOOLW + NGEMM12) {
        // ---- GEMM1+2 tile, by-major ordering ----
        int g  = b - NPOOLW;
        int by = g >> 4;           // 0..49
        int r  = g & 15;
        int ch = r >> 3;           // channel 0/1
        int bx = r & 7;            // col tile
        // wait until pool rows for t=2by,2by+1 of channel ch are complete
        if (tid == 0) {
            volatile int* cnt = d_cnt;
            int i0 = (2 * by) * 2 + ch, i1 = i0 + 2;
            while (cnt[i0] < 128 || cnt[i1] < 128) __nanosleep(200);
        }
        __syncthreads();
        __threadfence();

        const float* A = d_xp + (size_t)ch * T_STEPS * NBATCH * INSZ;
        const float* W = ch ? w2 : w1;
        const float* bias = ch ? b2 : b1;
        float* C = d_in12 + (size_t)ch * T_STEPS * NBATCH * HID;
        gemm_body(A, W, bias, C, by * BM, bx * BN, true);
    } else {
        // ---- transpose w_h2h3 -> d_wt ----
        __shared__ float tile[32][33];
        int bt = b - (NPOOLW + NGEMM12);   // 0..255
        int bx = (bt & 15) * 32, by = (bt >> 4) * 32;
        int tx = tid & 31, ty = tid >> 5;  // 32 x 8
#pragma unroll
        for (int r = 0; r < 4; r++)
            tile[ty + 8 * r][tx] = wh2h3[(size_t)(by + ty + 8 * r) * 512 + bx + tx];
        __syncthreads();
#pragma unroll
        for (int r = 0; r < 4; r++)
            d_wt[(size_t)(bx + ty + 8 * r) * 512 + by + tx] = tile[tx][ty + 8 * r];
    }
}

// ---------------------------------------------------------------------------
// GEMM3 standalone (round-13 structure)
// ---------------------------------------------------------------------------
__global__ __launch_bounds__(256, 3)
void gemm3_kernel(const float* __restrict__ w3, const float* __restrict__ b3) {
    gemm_body(d_s12, w3, b3, d_ff3, blockIdx.y * BM, blockIdx.x * BN, false);
}

// ---------------------------------------------------------------------------
// ALIF update: XLA HLO op-for-op — every op individually rounded, no FMA.
// ---------------------------------------------------------------------------
__device__ __forceinline__ void alif(float inp, float& m, float& s, float& bb,
                                     float alpha, float omAlpha, float ro, float omRo) {
    bb = __fadd_rn(__fmul_rn(ro, bb), __fmul_rn(omRo, s));
    float B = __fadd_rn(0.1f, __fmul_rn(1.8f, bb));
    float t1 = __fadd_rn(__fmul_rn(m, alpha), __fmul_rn(omAlpha, inp));
    m = __fsub_rn(t1, __fmul_rn(B, s));
    s = (__fsub_rn(m, B) > 0.f) ? 1.f : 0.f;
}

// ---------------------------------------------------------------------------
// Layers 1 & 2 scans — both layers per thread, depth-4 register rings (MLP 8)
// ---------------------------------------------------------------------------
__global__ void scan12_kernel(const float* __restrict__ tau_adp1, const float* __restrict__ tau_adp2,
                              const float* __restrict__ tau_m1,  const float* __restrict__ tau_m2) {
    int tid = blockIdx.x * blockDim.x + threadIdx.x;   // 32768
    int h = tid & 511;
    int n = tid >> 9;                                  // 0..63
    float alpha0 = alpha_of(tau_m1[h]),  ro0 = alpha_of(tau_adp1[h]);
    float alpha1 = alpha_of(tau_m2[h]),  ro1 = alpha_of(tau_adp2[h]);
    float omA0 = __fsub_rn(1.0f, alpha0), omR0 = __fsub_rn(1.0f, ro0);
    float omA1 = __fsub_rn(1.0f, alpha1), omR1 = __fsub_rn(1.0f, ro1);
    float m0 = 0.f, bb0 = 0.1f, s0 = 0.f;
    float m1 = 0.f, bb1 = 0.1f, s1 = 0.f;
    const float* in0 = d_in12 + (size_t)n * HID + h;
    const float* in1 = in0 + (size_t)T_STEPS * NBATCH * HID;
    float* sb = d_s12 + (size_t)n * INSZ + h;

    float buf0[4], buf1[4];
#pragma unroll
    for (int j = 0; j < 4; j++) {
        buf0[j] = in0[(size_t)j * NBATCH * HID];
        buf1[j] = in1[(size_t)j * NBATCH * HID];
    }
    for (int t = 0; t < T_STEPS; t++) {
        float i0 = buf0[t & 3], i1 = buf1[t & 3];
        if (t + 4 < T_STEPS) {
            buf0[t & 3] = in0[(size_t)(t + 4) * NBATCH * HID];
            buf1[t & 3] = in1[(size_t)(t + 4) * NBATCH * HID];
        }
        alif(i0, m0, s0, bb0, alpha0, omA0, ro0, omR0);
        alif(i1, m1, s1, bb1, alpha1, omA1, ro1, omR1);
        sb[(size_t)t * NBATCH * INSZ]       = s0;
        sb[(size_t)t * NBATCH * INSZ + HID] = s1;
    }
}

// ---------------------------------------------------------------------------
// Layer-3 sequential scan (round-13 structure, unchanged)
// ---------------------------------------------------------------------------
__global__ __launch_bounds__(128)
void layer3_kernel(const float* __restrict__ w_h2o3, const float* __restrict__ b_h2o3,
                   const float* __restrict__ b_h2h3,
                   const float* __restrict__ tau_adp, const float* __restrict__ tau_m,
                   float* __restrict__ out) {
    int n = blockIdx.x;
    int tid = threadIdx.x;
    int lane = tid & 31, wrp = tid >> 5;
    unsigned ltmask = (1u << lane) - 1u;
    __shared__ int   list[2][512];
    __shared__ int   wcnt[2][4];
    __shared__ float s3sm[512];

    float m[4], bb[4], s[4], alf[4], ro[4], omA[4], omR[4], b2[4];
#pragma unroll
    for (int k = 0; k < 4; k++) {
        int j = tid * 4 + k;
        alf[k] = alpha_of(tau_m[j]);
        ro[k]  = alpha_of(tau_adp[j]);
        omA[k] = __fsub_rn(1.0f, alf[k]);
        omR[k] = __fsub_rn(1.0f, ro[k]);
        b2[k]  = b_h2h3[j];
        m[k] = 0.f; bb[k] = 0.1f; s[k] = 0.f;
    }
    const float4* wt4 = (const float4*)d_wt;

    for (int t = 0; t < T_STEPS; t++) {
        int p = t & 1;
        unsigned bal[4];
#pragma unroll
        for (int k = 0; k < 4; k++)
            bal[k] = __ballot_sync(0xffffffffu, s[k] != 0.f);
        int offw = 0, cntw = 0;
#pragma unroll
        for (int k = 0; k < 4; k++) {
            offw += __popc(bal[k] & ltmask);
            cntw += __popc(bal[k]);
        }
        if (lane == 0) wcnt[p][wrp] = cntw;
        __syncthreads();
        int base = 0, total = 0;
#pragma unroll
        for (int w = 0; w < 4; w++) { int c = wcnt[p][w]; total += c; if (w < wrp) base += c; }
        int pos = base + offw;
#pragma unroll
        for (int k = 0; k < 4; k++)
            if (s[k] != 0.f) list[p][pos++] = tid * 4 + k;
        __syncthreads();

        float rec[4] = {0.f, 0.f, 0.f, 0.f};
#pragma unroll 4
        for (int e = 0; e < total; e++) {
            float4 wv = wt4[(size_t)list[p][e] * 128 + tid];
            rec[0] = __fadd_rn(rec[0], wv.x);
            rec[1] = __fadd_rn(rec[1], wv.y);
            rec[2] = __fadd_rn(rec[2], wv.z);
            rec[3] = __fadd_rn(rec[3], wv.w);
        }

        float4 ffv = *(const float4*)&d_ff3[((size_t)t * NBATCH + n) * HID + tid * 4];
        float ff[4] = {ffv.x, ffv.y, ffv.z, ffv.w};
#pragma unroll
        for (int k = 0; k < 4; k++) {
            float inp = __fadd_rn(__fadd_rn(ff[k], rec[k]), b2[k]);
            alif(inp, m[k], s[k], bb[k], alf[k], omA[k], ro[k], omR[k]);
        }
    }
#pragma unroll
    for (int k = 0; k < 4; k++) s3sm[tid * 4 + k] = s[k];
    __syncthreads();
    if (tid < 11) {
        float acc = 0.f;
        for (int j = 0; j < 512; j++)
            acc = __fmaf_rn(s3sm[j], w_h2o3[(size_t)tid * 512 + j], acc);
        out[n * 11 + tid] = __fadd_rn(acc, b_h2o3[tid]);
    }
}

// ---------------------------------------------------------------------------
extern "C" void kernel_launch(void* const* d_in, const int* in_sizes, int n_in,
                              void* d_out, int out_size) {
    const float* x          = (const float*)d_in[0];
    const float* w_i2h1     = (const float*)d_in[1];
    const float* b_i2h1     = (const float*)d_in[2];
    const float* w_i2h2     = (const float*)d_in[3];
    const float* b_i2h2     = (const float*)d_in[4];
    const float* w_i2h3     = (const float*)d_in[5];
    const float* b_i2h3     = (const float*)d_in[6];
    const float* w_h2h3     = (const float*)d_in[7];
    const float* b_h2h3     = (const float*)d_in[8];
    const float* w_h2o3     = (const float*)d_in[9];
    const float* b_h2o3     = (const float*)d_in[10];
    const float* tau_adp_h1 = (const float*)d_in[11];
    const float* tau_adp_h2 = (const float*)d_in[12];
    const float* tau_adp_h3 = (const float*)d_in[13];
    const float* tau_m_h1   = (const float*)d_in[14];
    const float* tau_m_h2   = (const float*)d_in[15];
    const float* tau_m_h3   = (const float*)d_in[16];
    float* out = (float*)d_out;

    void* cntPtr;
    cudaGetSymbolAddress(&cntPtr, d_cnt);
    cudaMemsetAsync(cntPtr, 0, sizeof(int) * 2 * T_STEPS);

    // Phase 1: pool + GEMM1+2 + transpose fused, overlapped via flags
    fused1_kernel<<<NPOOLW + NGEMM12 + 256, 256>>>(x, w_h2h3,
                                                   w_i2h1, b_i2h1, w_i2h2, b_i2h2);

    // Phase 2 (unchanged)
    scan12_kernel<<<128, 256>>>(tau_adp_h1, tau_adp_h2, tau_m_h1, tau_m_h2);

    gemm3_kernel<<<dim3(8, 50, 1), 256>>>(w_i2h3, b_i2h3);

    layer3_kernel<<<NBATCH, 128>>>(w_h2o3, b_h2o3, b_h2h3, tau_adp_h3, tau_m_h3, out);
}

// round 15
// speedup vs baseline: 1.1739x; 1.1739x over previous
#include <cuda_runtime.h>
#include <cuda_bf16.h>
#include <math.h>

// ---------------------------------------------------------------------------
// SRNN ALIF — bit-exact-vs-XLA-CPU fp32 (round 15).
// Phase 1 = round 13 (known 778.5): pool 2-out/thread + transpose fused launch,
// GEMM1+2 merged via blockIdx.z, GEMM3 separate; all GEMM math = serial
// ascending-k FFMA chains at the measured issue floor.
// layer3: latency surgery — ff3 ring prefetch + unroll-8 batched gather.
// ---------------------------------------------------------------------------

#define T_STEPS 100
#define NBATCH  64
#define HID     512
#define INSZ    1024

__device__ float d_xp  [2 * T_STEPS * NBATCH * INSZ];   // pooled [c][t][n][1024]
__device__ float d_in12[2 * T_STEPS * NBATCH * HID];    // ff proj [c][t][n][512]
__device__ float d_s12 [T_STEPS * NBATCH * INSZ];       // spikes s1||s2 [t][n][1024]
__device__ float d_ff3 [T_STEPS * NBATCH * HID];        // concat@W1 (+b1) [t][n][512]
__device__ float d_wt  [HID * HID];                     // w_h2h3 transposed [j][i]

// ---------------------------------------------------------------------------
// XLA:CPU exp — Cephes/Eigen pexp<float> with FMA, exact op order.
// ---------------------------------------------------------------------------
__device__ __forceinline__ float xla_expf(float x) {
    const float exp_hi = 88.723164f, exp_lo = -88.723164f;
    x = fminf(fmaxf(x, exp_lo), exp_hi);
    float m = floorf(__fmaf_rn(x, 1.44269504088896341f, 0.5f));
    float r = __fmaf_rn(m, -0.693359375f, x);
    r = __fmaf_rn(m, 2.12194440e-4f, r);
    float r2 = __fmul_rn(r, r);
    float y = 1.9875691500e-4f;
    y = __fmaf_rn(y, r, 1.3981999507e-3f);
    y = __fmaf_rn(y, r, 8.3334519073e-3f);
    y = __fmaf_rn(y, r, 4.1665795894e-2f);
    y = __fmaf_rn(y, r, 1.6666665459e-1f);
    y = __fmaf_rn(y, r, 5.0000001201e-1f);
    y = __fmaf_rn(y, r2, r);
    y = __fadd_rn(y, 1.0f);
    return ldexpf(y, (int)m);
}

__device__ __forceinline__ float alpha_of(float tau) {
    return xla_expf(__fdiv_rn(-1.0f, tau));
}

// ---------------------------------------------------------------------------
// 1) maxpool 4x4 stride 4 (exact), 2 outputs/thread (MLP 8) + transpose of
//    w_h2h3 folded in. Blocks [0,25600): pool; [25600,25856): transpose.
// ---------------------------------------------------------------------------
__device__ __forceinline__ const float* pool_src(int out, const float* x) {
    int i    = out & 1023;
    int n    = (out >> 10) & 63;
    int rest = out >> 16;          // c*100 + t
    int t    = rest % 100;
    int c    = rest / 100;
    int ph = i >> 5, pw = i & 31;
    return x + (((size_t)(n * 100 + t) * 2 + c) << 14) + ph * 512 + pw * 4;
}

__global__ void pool_tr_kernel(const float* __restrict__ x,
                               const float* __restrict__ w) {
    if (blockIdx.x < 25600) {
        int out0 = blockIdx.x * 512 + threadIdx.x;
        int out1 = out0 + 256;
        const float* b0 = pool_src(out0, x);
        const float* b1 = pool_src(out1, x);
        float4 v[8];
#pragma unroll
        for (int r = 0; r < 4; r++) {
            v[r]     = *(const float4*)(b0 + r * 128);
            v[r + 4] = *(const float4*)(b1 + r * 128);
        }
        float mx0 = -3.4e38f, mx1 = -3.4e38f;
#pragma unroll
        for (int r = 0; r < 4; r++) {
            mx0 = fmaxf(mx0, fmaxf(fmaxf(v[r].x, v[r].y), fmaxf(v[r].z, v[r].w)));
            mx1 = fmaxf(mx1, fmaxf(fmaxf(v[r+4].x, v[r+4].y), fmaxf(v[r+4].z, v[r+4].w)));
        }
        d_xp[out0] = mx0;
        d_xp[out1] = mx1;
    } else {
        __shared__ float tile[32][33];
        int b  = blockIdx.x - 25600;       // 0..255
        int bx = (b & 15) * 32, by = (b >> 4) * 32;
        int tx = threadIdx.x & 31, ty = threadIdx.x >> 5;   // 32 x 8
#pragma unroll
        for (int r = 0; r < 4; r++)
            tile[ty + 8 * r][tx] = w[(size_t)(by + ty + 8 * r) * 512 + bx + tx];
        __syncthreads();
#pragma unroll
        for (int r = 0; r < 4; r++)
            d_wt[(size_t)(bx + ty + 8 * r) * 512 + by + tx] = tile[tx][ty + 8 * r];
    }
}

// ---------------------------------------------------------------------------
// 2) fp32 GEMM (NT), BM=128 BN=64 BK=16, 8x4 micro-tile, serial ascending-k
//    FFMA per output, ping-pong smem + register prefetch, peeled final iter.
// ---------------------------------------------------------------------------
#define BM 128
#define BN 64
#define BK 16

__device__ __forceinline__ void gemm_compute_tile(
    const float As[BK][BM], const float Ws[BK][BN],
    int ty, int tx, float acc[8][4]) {
#pragma unroll
    for (int k = 0; k < BK; k++) {
        float a[8], w[4];
#pragma unroll
        for (int r = 0; r < 8; r++) a[r] = As[k][ty * 8 + r];
#pragma unroll
        for (int cI = 0; cI < 4; cI++) w[cI] = Ws[k][tx * 4 + cI];
#pragma unroll
        for (int r = 0; r < 8; r++)
#pragma unroll
            for (int cI = 0; cI < 4; cI++)
                acc[r][cI] = __fmaf_rn(a[r], w[cI], acc[r][cI]);
    }
}

__global__ __launch_bounds__(256, 3)
void gemm_nt(const float* __restrict__ A0, const float* __restrict__ A1,
             const float* __restrict__ W0, const float* __restrict__ W1,
             const float* __restrict__ b0, const float* __restrict__ b1,
             float* __restrict__ C0, float* __restrict__ C1) {
    __shared__ float As[2][BK][BM];
    __shared__ float Ws[2][BK][BN];
    int ch = blockIdx.z;
    const float* A = ch ? A1 : A0;
    const float* W = ch ? W1 : W0;
    const float* bias_a = ch ? b1 : b0;
    float* C = ch ? C1 : C0;

    int tid = threadIdx.x;
    int rowBase = blockIdx.y * BM;
    int colBase = blockIdx.x * BN;
    int tx = tid & 15;
    int ty = tid >> 4;
    int mA0 = (tid * 2)     >> 2, kqA0 = (tid * 2)     & 3;
    int mA1 = (tid * 2 + 1) >> 2, kqA1 = (tid * 2 + 1) & 3;
    int nW  = tid >> 2,           kqW  = tid & 3;
    const float* Arow0 = A + (size_t)(rowBase + mA0) * 1024 + kqA0 * 4;
    const float* Arow1 = A + (size_t)(rowBase + mA1) * 1024 + kqA1 * 4;
    const float* Wrow  = W + (size_t)(colBase + nW)  * 1024 + kqW  * 4;

    float acc[8][4];
#pragma unroll
    for (int r = 0; r < 8; r++)
#pragma unroll
        for (int cI = 0; cI < 4; cI++) acc[r][cI] = 0.f;

    {
        float4 v0 = *(const float4*)Arow0;
        float4 v1 = *(const float4*)Arow1;
        float4 vw = *(const float4*)Wrow;
        As[0][kqA0 * 4 + 0][mA0] = v0.x; As[0][kqA0 * 4 + 1][mA0] = v0.y;
        As[0][kqA0 * 4 + 2][mA0] = v0.z; As[0][kqA0 * 4 + 3][mA0] = v0.w;
        As[0][kqA1 * 4 + 0][mA1] = v1.x; As[0][kqA1 * 4 + 1][mA1] = v1.y;
        As[0][kqA1 * 4 + 2][mA1] = v1.z; As[0][kqA1 * 4 + 3][mA1] = v1.w;
        Ws[0][kqW * 4 + 0][nW] = vw.x; Ws[0][kqW * 4 + 1][nW] = vw.y;
        Ws[0][kqW * 4 + 2][nW] = vw.z; Ws[0][kqW * 4 + 3][nW] = vw.w;
    }
    __syncthreads();

    for (int it = 0; it < 63; ++it) {
        int cur = it & 1, nb = 1 - cur;
        int koff = (it + 1) * BK;
        float4 v0 = *(const float4*)(Arow0 + koff);
        float4 v1 = *(const float4*)(Arow1 + koff);
        float4 vw = *(const float4*)(Wrow  + koff);

        gemm_compute_tile(As[cur], Ws[cur], ty, tx, acc);

        As[nb][kqA0 * 4 + 0][mA0] = v0.x; As[nb][kqA0 * 4 + 1][mA0] = v0.y;
        As[nb][kqA0 * 4 + 2][mA0] = v0.z; As[nb][kqA0 * 4 + 3][mA0] = v0.w;
        As[nb][kqA1 * 4 + 0][mA1] = v1.x; As[nb][kqA1 * 4 + 1][mA1] = v1.y;
        As[nb][kqA1 * 4 + 2][mA1] = v1.z; As[nb][kqA1 * 4 + 3][mA1] = v1.w;
        Ws[nb][kqW * 4 + 0][nW] = vw.x; Ws[nb][kqW * 4 + 1][nW] = vw.y;
        Ws[nb][kqW * 4 + 2][nW] = vw.z; Ws[nb][kqW * 4 + 3][nW] = vw.w;
        __syncthreads();
    }
    gemm_compute_tile(As[1], Ws[1], ty, tx, acc);

    float badd[4];
#pragma unroll
    for (int cI = 0; cI < 4; cI++)
        badd[cI] = bias_a ? bias_a[colBase + tx * 4 + cI] : 0.f;
#pragma unroll
    for (int r = 0; r < 8; r++) {
        size_t rowOff = (size_t)(rowBase + ty * 8 + r) * 512 + colBase + tx * 4;
#pragma unroll
        for (int cI = 0; cI < 4; cI++)
            C[rowOff + cI] = __fadd_rn(acc[r][cI], badd[cI]);
    }
}

// ---------------------------------------------------------------------------
// ALIF update: XLA HLO op-for-op — every op individually rounded, no FMA.
// ---------------------------------------------------------------------------
__device__ __forceinline__ void alif(float inp, float& m, float& s, float& bb,
                                     float alpha, float omAlpha, float ro, float omRo) {
    bb = __fadd_rn(__fmul_rn(ro, bb), __fmul_rn(omRo, s));
    float B = __fadd_rn(0.1f, __fmul_rn(1.8f, bb));
    float t1 = __fadd_rn(__fmul_rn(m, alpha), __fmul_rn(omAlpha, inp));
    m = __fsub_rn(t1, __fmul_rn(B, s));
    s = (__fsub_rn(m, B) > 0.f) ? 1.f : 0.f;
}

// ---------------------------------------------------------------------------
// 3) Layers 1 & 2 scans — BOTH layers per thread (2 chains, MLP 8),
//    depth-4 register rings (4 divides T=100 -> stays in registers).
// ---------------------------------------------------------------------------
__global__ void scan12_kernel(const float* __restrict__ tau_adp1, const float* __restrict__ tau_adp2,
                              const float* __restrict__ tau_m1,  const float* __restrict__ tau_m2) {
    int tid = blockIdx.x * blockDim.x + threadIdx.x;   // 32768
    int h = tid & 511;
    int n = tid >> 9;                                  // 0..63
    float alpha0 = alpha_of(tau_m1[h]),  ro0 = alpha_of(tau_adp1[h]);
    float alpha1 = alpha_of(tau_m2[h]),  ro1 = alpha_of(tau_adp2[h]);
    float omA0 = __fsub_rn(1.0f, alpha0), omR0 = __fsub_rn(1.0f, ro0);
    float omA1 = __fsub_rn(1.0f, alpha1), omR1 = __fsub_rn(1.0f, ro1);
    float m0 = 0.f, bb0 = 0.1f, s0 = 0.f;
    float m1 = 0.f, bb1 = 0.1f, s1 = 0.f;
    const float* in0 = d_in12 + (size_t)n * HID + h;
    const float* in1 = in0 + (size_t)T_STEPS * NBATCH * HID;
    float* sb = d_s12 + (size_t)n * INSZ + h;

    float buf0[4], buf1[4];
#pragma unroll
    for (int j = 0; j < 4; j++) {
        buf0[j] = in0[(size_t)j * NBATCH * HID];
        buf1[j] = in1[(size_t)j * NBATCH * HID];
    }
    for (int t = 0; t < T_STEPS; t++) {
        float i0 = buf0[t & 3], i1 = buf1[t & 3];
        if (t + 4 < T_STEPS) {
            buf0[t & 3] = in0[(size_t)(t + 4) * NBATCH * HID];
            buf1[t & 3] = in1[(size_t)(t + 4) * NBATCH * HID];
        }
        alif(i0, m0, s0, bb0, alpha0, omA0, ro0, omR0);
        alif(i1, m1, s1, bb1, alpha1, omA1, ro1, omR1);
        sb[(size_t)t * NBATCH * INSZ]       = s0;
        sb[(size_t)t * NBATCH * INSZ + HID] = s1;
    }
}

// ---------------------------------------------------------------------------
// 4) Layer-3 sequential scan. One CTA/batch, 128 threads x 4 neurons.
//    Latency-optimized: ff3 ring prefetch (t+1 issued at top of step t),
//    gather unroll-8 (8 LDS + 8 LDG.128 batched, then 32 FADDs in exact
//    serial ascending-e order per neuron — bit-identical chain).
// ---------------------------------------------------------------------------
__global__ __launch_bounds__(128)
void layer3_kernel(const float* __restrict__ w_h2o3, const float* __restrict__ b_h2o3,
                   const float* __restrict__ b_h2h3,
                   const float* __restrict__ tau_adp, const float* __restrict__ tau_m,
                   float* __restrict__ out) {
    int n = blockIdx.x;
    int tid = threadIdx.x;          // neurons 4*tid .. 4*tid+3
    int lane = tid & 31, wrp = tid >> 5;
    unsigned ltmask = (1u << lane) - 1u;
    __shared__ int   list[2][512];
    __shared__ int   wcnt[2][4];
    __shared__ float s3sm[512];

    float m[4], bb[4], s[4], alf[4], ro[4], omA[4], omR[4], b2[4];
#pragma unroll
    for (int k = 0; k < 4; k++) {
        int j = tid * 4 + k;
        alf[k] = alpha_of(tau_m[j]);
        ro[k]  = alpha_of(tau_adp[j]);
        omA[k] = __fsub_rn(1.0f, alf[k]);
        omR[k] = __fsub_rn(1.0f, ro[k]);
        b2[k]  = b_h2h3[j];          // zero in practice
        m[k] = 0.f; bb[k] = 0.1f; s[k] = 0.f;
    }
    const float4* wt4 = (const float4*)d_wt;   // [j][i/4] float4
    const float4* ff4 = (const float4*)d_ff3;  // [(t*64+n)*128 + tid]

    float4 ffv = ff4[(size_t)n * 128 + tid];   // t = 0

    for (int t = 0; t < T_STEPS; t++) {
        // prefetch next step's ff values — overlaps ballot/compaction/gather
        float4 ffn;
        if (t + 1 < T_STEPS) ffn = ff4[((size_t)(t + 1) * NBATCH + n) * 128 + tid];

        int p = t & 1;
        unsigned bal[4];
#pragma unroll
        for (int k = 0; k < 4; k++)
            bal[k] = __ballot_sync(0xffffffffu, s[k] != 0.f);
        int offw = 0, cntw = 0;
#pragma unroll
        for (int k = 0; k < 4; k++) {
            offw += __popc(bal[k] & ltmask);
            cntw += __popc(bal[k]);
        }
        if (lane == 0) wcnt[p][wrp] = cntw;
        __syncthreads();
        int base = 0, total = 0;
#pragma unroll
        for (int w = 0; w < 4; w++) { int c = wcnt[p][w]; total += c; if (w < wrp) base += c; }
        int pos = base + offw;
#pragma unroll
        for (int k = 0; k < 4; k++)            // own actives, k ascending -> j ascending
            if (s[k] != 0.f) list[p][pos++] = tid * 4 + k;
        __syncthreads();

        // serial ascending-e chain per neuron; loads batched 8-wide (MLP 8)
        float rec[4] = {0.f, 0.f, 0.f, 0.f};
        int e = 0;
        for (; e + 8 <= total; e += 8) {
            float4 v[8];
#pragma unroll
            for (int u = 0; u < 8; u++)
                v[u] = wt4[(size_t)list[p][e + u] * 128 + tid];
#pragma unroll
            for (int u = 0; u < 8; u++) {
                rec[0] = __fadd_rn(rec[0], v[u].x);
                rec[1] = __fadd_rn(rec[1], v[u].y);
                rec[2] = __fadd_rn(rec[2], v[u].z);
                rec[3] = __fadd_rn(rec[3], v[u].w);
            }
        }
        for (; e < total; e++) {
            float4 wv = wt4[(size_t)list[p][e] * 128 + tid];
            rec[0] = __fadd_rn(rec[0], wv.x);
            rec[1] = __fadd_rn(rec[1], wv.y);
            rec[2] = __fadd_rn(rec[2], wv.z);
            rec[3] = __fadd_rn(rec[3], wv.w);
        }

        float ff[4] = {ffv.x, ffv.y, ffv.z, ffv.w};
#pragma unroll
        for (int k = 0; k < 4; k++) {
            float inp = __fadd_rn(__fadd_rn(ff[k], rec[k]), b2[k]);
            alif(inp, m[k], s[k], bb[k], alf[k], omA[k], ro[k], omR[k]);
        }
        ffv = ffn;
    }
#pragma unroll
    for (int k = 0; k < 4; k++) s3sm[tid * 4 + k] = s[k];
    __syncthreads();
    if (tid < 11) {
        float acc = 0.f;
        for (int j = 0; j < 512; j++)
            acc = __fmaf_rn(s3sm[j], w_h2o3[(size_t)tid * 512 + j], acc);
        out[n * 11 + tid] = __fadd_rn(acc, b_h2o3[tid]);
    }
}

// ---------------------------------------------------------------------------
extern "C" void kernel_launch(void* const* d_in, const int* in_sizes, int n_in,
                              void* d_out, int out_size) {
    const float* x          = (const float*)d_in[0];
    const float* w_i2h1     = (const float*)d_in[1];
    const float* b_i2h1     = (const float*)d_in[2];
    const float* w_i2h2     = (const float*)d_in[3];
    const float* b_i2h2     = (const float*)d_in[4];
    const float* w_i2h3     = (const float*)d_in[5];
    const float* b_i2h3     = (const float*)d_in[6];
    const float* w_h2h3     = (const float*)d_in[7];
    const float* b_h2h3     = (const float*)d_in[8];
    const float* w_h2o3     = (const float*)d_in[9];
    const float* b_h2o3     = (const float*)d_in[10];
    const float* tau_adp_h1 = (const float*)d_in[11];
    const float* tau_adp_h2 = (const float*)d_in[12];
    const float* tau_adp_h3 = (const float*)d_in[13];
    const float* tau_m_h1   = (const float*)d_in[14];
    const float* tau_m_h2   = (const float*)d_in[15];
    const float* tau_m_h3   = (const float*)d_in[16];
    float* out = (float*)d_out;

    float *xp, *in12, *s12, *ff3;
    cudaGetSymbolAddress((void**)&xp,   d_xp);
    cudaGetSymbolAddress((void**)&in12, d_in12);
    cudaGetSymbolAddress((void**)&s12,  d_s12);
    cudaGetSymbolAddress((void**)&ff3,  d_ff3);

    pool_tr_kernel<<<25856, 256>>>(x, w_h2h3);   // pool (2 out/thread) + transpose

    // merged GEMM1+2: grid (8 col-tiles, 50 row-tiles, 2 channels) = 800 CTAs
    gemm_nt<<<dim3(8, 50, 2), 256>>>(
        xp, xp + (size_t)T_STEPS * NBATCH * INSZ,
        w_i2h1, w_i2h2, b_i2h1, b_i2h2,
        in12, in12 + (size_t)T_STEPS * NBATCH * HID);

    scan12_kernel<<<128, 256>>>(tau_adp_h1, tau_adp_h2, tau_m_h1, tau_m_h2);

    // GEMM3: 400 CTAs -> single wave at 3 CTAs/SM
    gemm_nt<<<dim3(8, 50, 1), 256>>>(
        s12, s12, w_i2h3, w_i2h3, b_i2h3, b_i2h3, ff3, ff3);

    layer3_kernel<<<NBATCH, 128>>>(w_h2o3, b_h2o3, b_h2h3, tau_adp_h3, tau_m_h3, out);
}

// round 16
// speedup vs baseline: 1.1774x; 1.0030x over previous
#include <cuda_runtime.h>
#include <cuda_bf16.h>
#include <math.h>

// ---------------------------------------------------------------------------
// SRNN ALIF — bit-exact-vs-XLA-CPU fp32 (round 16).
// = round 15 (best, 758.3) with layer3 gather upgraded to unroll-16 batching
// (2 exposed L2 rounds/step instead of 4; FADD chains bit-identical).
// ---------------------------------------------------------------------------

#define T_STEPS 100
#define NBATCH  64
#define HID     512
#define INSZ    1024

__device__ float d_xp  [2 * T_STEPS * NBATCH * INSZ];   // pooled [c][t][n][1024]
__device__ float d_in12[2 * T_STEPS * NBATCH * HID];    // ff proj [c][t][n][512]
__device__ float d_s12 [T_STEPS * NBATCH * INSZ];       // spikes s1||s2 [t][n][1024]
__device__ float d_ff3 [T_STEPS * NBATCH * HID];        // concat@W1 (+b1) [t][n][512]
__device__ float d_wt  [HID * HID];                     // w_h2h3 transposed [j][i]

// ---------------------------------------------------------------------------
// XLA:CPU exp — Cephes/Eigen pexp<float> with FMA, exact op order.
// ---------------------------------------------------------------------------
__device__ __forceinline__ float xla_expf(float x) {
    const float exp_hi = 88.723164f, exp_lo = -88.723164f;
    x = fminf(fmaxf(x, exp_lo), exp_hi);
    float m = floorf(__fmaf_rn(x, 1.44269504088896341f, 0.5f));
    float r = __fmaf_rn(m, -0.693359375f, x);
    r = __fmaf_rn(m, 2.12194440e-4f, r);
    float r2 = __fmul_rn(r, r);
    float y = 1.9875691500e-4f;
    y = __fmaf_rn(y, r, 1.3981999507e-3f);
    y = __fmaf_rn(y, r, 8.3334519073e-3f);
    y = __fmaf_rn(y, r, 4.1665795894e-2f);
    y = __fmaf_rn(y, r, 1.6666665459e-1f);
    y = __fmaf_rn(y, r, 5.0000001201e-1f);
    y = __fmaf_rn(y, r2, r);
    y = __fadd_rn(y, 1.0f);
    return ldexpf(y, (int)m);
}

__device__ __forceinline__ float alpha_of(float tau) {
    return xla_expf(__fdiv_rn(-1.0f, tau));
}

// ---------------------------------------------------------------------------
// 1) maxpool 4x4 stride 4 (exact), 2 outputs/thread (MLP 8) + transpose of
//    w_h2h3 folded in. Blocks [0,25600): pool; [25600,25856): transpose.
// ---------------------------------------------------------------------------
__device__ __forceinline__ const float* pool_src(int out, const float* x) {
    int i    = out & 1023;
    int n    = (out >> 10) & 63;
    int rest = out >> 16;          // c*100 + t
    int t    = rest % 100;
    int c    = rest / 100;
    int ph = i >> 5, pw = i & 31;
    return x + (((size_t)(n * 100 + t) * 2 + c) << 14) + ph * 512 + pw * 4;
}

__global__ void pool_tr_kernel(const float* __restrict__ x,
                               const float* __restrict__ w) {
    if (blockIdx.x < 25600) {
        int out0 = blockIdx.x * 512 + threadIdx.x;
        int out1 = out0 + 256;
        const float* b0 = pool_src(out0, x);
        const float* b1 = pool_src(out1, x);
        float4 v[8];
#pragma unroll
        for (int r = 0; r < 4; r++) {
            v[r]     = *(const float4*)(b0 + r * 128);
            v[r + 4] = *(const float4*)(b1 + r * 128);
        }
        float mx0 = -3.4e38f, mx1 = -3.4e38f;
#pragma unroll
        for (int r = 0; r < 4; r++) {
            mx0 = fmaxf(mx0, fmaxf(fmaxf(v[r].x, v[r].y), fmaxf(v[r].z, v[r].w)));
            mx1 = fmaxf(mx1, fmaxf(fmaxf(v[r+4].x, v[r+4].y), fmaxf(v[r+4].z, v[r+4].w)));
        }
        d_xp[out0] = mx0;
        d_xp[out1] = mx1;
    } else {
        __shared__ float tile[32][33];
        int b  = blockIdx.x - 25600;       // 0..255
        int bx = (b & 15) * 32, by = (b >> 4) * 32;
        int tx = threadIdx.x & 31, ty = threadIdx.x >> 5;   // 32 x 8
#pragma unroll
        for (int r = 0; r < 4; r++)
            tile[ty + 8 * r][tx] = w[(size_t)(by + ty + 8 * r) * 512 + bx + tx];
        __syncthreads();
#pragma unroll
        for (int r = 0; r < 4; r++)
            d_wt[(size_t)(bx + ty + 8 * r) * 512 + by + tx] = tile[tx][ty + 8 * r];
    }
}

// ---------------------------------------------------------------------------
// 2) fp32 GEMM (NT), BM=128 BN=64 BK=16, 8x4 micro-tile, serial ascending-k
//    FFMA per output, ping-pong smem + register prefetch, peeled final iter.
// ---------------------------------------------------------------------------
#define BM 128
#define BN 64
#define BK 16

__device__ __forceinline__ void gemm_compute_tile(
    const float As[BK][BM], const float Ws[BK][BN],
    int ty, int tx, float acc[8][4]) {
#pragma unroll
    for (int k = 0; k < BK; k++) {
        float a[8], w[4];
#pragma unroll
        for (int r = 0; r < 8; r++) a[r] = As[k][ty * 8 + r];
#pragma unroll
        for (int cI = 0; cI < 4; cI++) w[cI] = Ws[k][tx * 4 + cI];
#pragma unroll
        for (int r = 0; r < 8; r++)
#pragma unroll
            for (int cI = 0; cI < 4; cI++)
                acc[r][cI] = __fmaf_rn(a[r], w[cI], acc[r][cI]);
    }
}

__global__ __launch_bounds__(256, 3)
void gemm_nt(const float* __restrict__ A0, const float* __restrict__ A1,
             const float* __restrict__ W0, const float* __restrict__ W1,
             const float* __restrict__ b0, const float* __restrict__ b1,
             float* __restrict__ C0, float* __restrict__ C1) {
    __shared__ float As[2][BK][BM];
    __shared__ float Ws[2][BK][BN];
    int ch = blockIdx.z;
    const float* A = ch ? A1 : A0;
    const float* W = ch ? W1 : W0;
    const float* bias_a = ch ? b1 : b0;
    float* C = ch ? C1 : C0;

    int tid = threadIdx.x;
    int rowBase = blockIdx.y * BM;
    int colBase = blockIdx.x * BN;
    int tx = tid & 15;
    int ty = tid >> 4;
    int mA0 = (tid * 2)     >> 2, kqA0 = (tid * 2)     & 3;
    int mA1 = (tid * 2 + 1) >> 2, kqA1 = (tid * 2 + 1) & 3;
    int nW  = tid >> 2,           kqW  = tid & 3;
    const float* Arow0 = A + (size_t)(rowBase + mA0) * 1024 + kqA0 * 4;
    const float* Arow1 = A + (size_t)(rowBase + mA1) * 1024 + kqA1 * 4;
    const float* Wrow  = W + (size_t)(colBase + nW)  * 1024 + kqW  * 4;

    float acc[8][4];
#pragma unroll
    for (int r = 0; r < 8; r++)
#pragma unroll
        for (int cI = 0; cI < 4; cI++) acc[r][cI] = 0.f;

    {
        float4 v0 = *(const float4*)Arow0;
        float4 v1 = *(const float4*)Arow1;
        float4 vw = *(const float4*)Wrow;
        As[0][kqA0 * 4 + 0][mA0] = v0.x; As[0][kqA0 * 4 + 1][mA0] = v0.y;
        As[0][kqA0 * 4 + 2][mA0] = v0.z; As[0][kqA0 * 4 + 3][mA0] = v0.w;
        As[0][kqA1 * 4 + 0][mA1] = v1.x; As[0][kqA1 * 4 + 1][mA1] = v1.y;
        As[0][kqA1 * 4 + 2][mA1] = v1.z; As[0][kqA1 * 4 + 3][mA1] = v1.w;
        Ws[0][kqW * 4 + 0][nW] = vw.x; Ws[0][kqW * 4 + 1][nW] = vw.y;
        Ws[0][kqW * 4 + 2][nW] = vw.z; Ws[0][kqW * 4 + 3][nW] = vw.w;
    }
    __syncthreads();

    for (int it = 0; it < 63; ++it) {
        int cur = it & 1, nb = 1 - cur;
        int koff = (it + 1) * BK;
        float4 v0 = *(const float4*)(Arow0 + koff);
        float4 v1 = *(const float4*)(Arow1 + koff);
        float4 vw = *(const float4*)(Wrow  + koff);

        gemm_compute_tile(As[cur], Ws[cur], ty, tx, acc);

        As[nb][kqA0 * 4 + 0][mA0] = v0.x; As[nb][kqA0 * 4 + 1][mA0] = v0.y;
        As[nb][kqA0 * 4 + 2][mA0] = v0.z; As[nb][kqA0 * 4 + 3][mA0] = v0.w;
        As[nb][kqA1 * 4 + 0][mA1] = v1.x; As[nb][kqA1 * 4 + 1][mA1] = v1.y;
        As[nb][kqA1 * 4 + 2][mA1] = v1.z; As[nb][kqA1 * 4 + 3][mA1] = v1.w;
        Ws[nb][kqW * 4 + 0][nW] = vw.x; Ws[nb][kqW * 4 + 1][nW] = vw.y;
        Ws[nb][kqW * 4 + 2][nW] = vw.z; Ws[nb][kqW * 4 + 3][nW] = vw.w;
        __syncthreads();
    }
    gemm_compute_tile(As[1], Ws[1], ty, tx, acc);

    float badd[4];
#pragma unroll
    for (int cI = 0; cI < 4; cI++)
        badd[cI] = bias_a ? bias_a[colBase + tx * 4 + cI] : 0.f;
#pragma unroll
    for (int r = 0; r < 8; r++) {
        size_t rowOff = (size_t)(rowBase + ty * 8 + r) * 512 + colBase + tx * 4;
#pragma unroll
        for (int cI = 0; cI < 4; cI++)
            C[rowOff + cI] = __fadd_rn(acc[r][cI], badd[cI]);
    }
}

// ---------------------------------------------------------------------------
// ALIF update: XLA HLO op-for-op — every op individually rounded, no FMA.
// ---------------------------------------------------------------------------
__device__ __forceinline__ void alif(float inp, float& m, float& s, float& bb,
                                     float alpha, float omAlpha, float ro, float omRo) {
    bb = __fadd_rn(__fmul_rn(ro, bb), __fmul_rn(omRo, s));
    float B = __fadd_rn(0.1f, __fmul_rn(1.8f, bb));
    float t1 = __fadd_rn(__fmul_rn(m, alpha), __fmul_rn(omAlpha, inp));
    m = __fsub_rn(t1, __fmul_rn(B, s));
    s = (__fsub_rn(m, B) > 0.f) ? 1.f : 0.f;
}

// ---------------------------------------------------------------------------
// 3) Layers 1 & 2 scans — BOTH layers per thread (2 chains, MLP 8),
//    depth-4 register rings (4 divides T=100 -> stays in registers).
// ---------------------------------------------------------------------------
__global__ void scan12_kernel(const float* __restrict__ tau_adp1, const float* __restrict__ tau_adp2,
                              const float* __restrict__ tau_m1,  const float* __restrict__ tau_m2) {
    int tid = blockIdx.x * blockDim.x + threadIdx.x;   // 32768
    int h = tid & 511;
    int n = tid >> 9;                                  // 0..63
    float alpha0 = alpha_of(tau_m1[h]),  ro0 = alpha_of(tau_adp1[h]);
    float alpha1 = alpha_of(tau_m2[h]),  ro1 = alpha_of(tau_adp2[h]);
    float omA0 = __fsub_rn(1.0f, alpha0), omR0 = __fsub_rn(1.0f, ro0);
    float omA1 = __fsub_rn(1.0f, alpha1), omR1 = __fsub_rn(1.0f, ro1);
    float m0 = 0.f, bb0 = 0.1f, s0 = 0.f;
    float m1 = 0.f, bb1 = 0.1f, s1 = 0.f;
    const float* in0 = d_in12 + (size_t)n * HID + h;
    const float* in1 = in0 + (size_t)T_STEPS * NBATCH * HID;
    float* sb = d_s12 + (size_t)n * INSZ + h;

    float buf0[4], buf1[4];
#pragma unroll
    for (int j = 0; j < 4; j++) {
        buf0[j] = in0[(size_t)j * NBATCH * HID];
        buf1[j] = in1[(size_t)j * NBATCH * HID];
    }
    for (int t = 0; t < T_STEPS; t++) {
        float i0 = buf0[t & 3], i1 = buf1[t & 3];
        if (t + 4 < T_STEPS) {
            buf0[t & 3] = in0[(size_t)(t + 4) * NBATCH * HID];
            buf1[t & 3] = in1[(size_t)(t + 4) * NBATCH * HID];
        }
        alif(i0, m0, s0, bb0, alpha0, omA0, ro0, omR0);
        alif(i1, m1, s1, bb1, alpha1, omA1, ro1, omR1);
        sb[(size_t)t * NBATCH * INSZ]       = s0;
        sb[(size_t)t * NBATCH * INSZ + HID] = s1;
    }
}

// ---------------------------------------------------------------------------
// 4) Layer-3 sequential scan. One CTA/batch, 128 threads x 4 neurons.
//    ff3 ring prefetch; gather batched unroll-16 (then 4, then 1) — all FADDs
//    in exact serial ascending-e order per neuron (bit-identical chain).
// ---------------------------------------------------------------------------
__global__ __launch_bounds__(128)
void layer3_kernel(const float* __restrict__ w_h2o3, const float* __restrict__ b_h2o3,
                   const float* __restrict__ b_h2h3,
                   const float* __restrict__ tau_adp, const float* __restrict__ tau_m,
                   float* __restrict__ out) {
    int n = blockIdx.x;
    int tid = threadIdx.x;          // neurons 4*tid .. 4*tid+3
    int lane = tid & 31, wrp = tid >> 5;
    unsigned ltmask = (1u << lane) - 1u;
    __shared__ int   list[2][512];
    __shared__ int   wcnt[2][4];
    __shared__ float s3sm[512];

    float m[4], bb[4], s[4], alf[4], ro[4], omA[4], omR[4], b2[4];
#pragma unroll
    for (int k = 0; k < 4; k++) {
        int j = tid * 4 + k;
        alf[k] = alpha_of(tau_m[j]);
        ro[k]  = alpha_of(tau_adp[j]);
        omA[k] = __fsub_rn(1.0f, alf[k]);
        omR[k] = __fsub_rn(1.0f, ro[k]);
        b2[k]  = b_h2h3[j];          // zero in practice
        m[k] = 0.f; bb[k] = 0.1f; s[k] = 0.f;
    }
    const float4* wt4 = (const float4*)d_wt;   // [j][i/4] float4
    const float4* ff4 = (const float4*)d_ff3;  // [(t*64+n)*128 + tid]

    float4 ffv = ff4[(size_t)n * 128 + tid];   // t = 0

    for (int t = 0; t < T_STEPS; t++) {
        // prefetch next step's ff values — overlaps ballot/compaction/gather
        float4 ffn;
        if (t + 1 < T_STEPS) ffn = ff4[((size_t)(t + 1) * NBATCH + n) * 128 + tid];

        int p = t & 1;
        unsigned bal[4];
#pragma unroll
        for (int k = 0; k < 4; k++)
            bal[k] = __ballot_sync(0xffffffffu, s[k] != 0.f);
        int offw = 0, cntw = 0;
#pragma unroll
        for (int k = 0; k < 4; k++) {
            offw += __popc(bal[k] & ltmask);
            cntw += __popc(bal[k]);
        }
        if (lane == 0) wcnt[p][wrp] = cntw;
        __syncthreads();
        int base = 0, total = 0;
#pragma unroll
        for (int w = 0; w < 4; w++) { int c = wcnt[p][w]; total += c; if (w < wrp) base += c; }
        int pos = base + offw;
#pragma unroll
        for (int k = 0; k < 4; k++)            // own actives, k ascending -> j ascending
            if (s[k] != 0.f) list[p][pos++] = tid * 4 + k;
        __syncthreads();

        // serial ascending-e chain per neuron; loads batched 16-wide (MLP 16)
        float rec[4] = {0.f, 0.f, 0.f, 0.f};
        int e = 0;
        for (; e + 16 <= total; e += 16) {
            float4 v[16];
#pragma unroll
            for (int u = 0; u < 16; u++)
                v[u] = wt4[(size_t)list[p][e + u] * 128 + tid];
#pragma unroll
            for (int u = 0; u < 16; u++) {
                rec[0] = __fadd_rn(rec[0], v[u].x);
                rec[1] = __fadd_rn(rec[1], v[u].y);
                rec[2] = __fadd_rn(rec[2], v[u].z);
                rec[3] = __fadd_rn(rec[3], v[u].w);
            }
        }
        for (; e + 4 <= total; e += 4) {
            float4 v[4];
#pragma unroll
            for (int u = 0; u < 4; u++)
                v[u] = wt4[(size_t)list[p][e + u] * 128 + tid];
#pragma unroll
            for (int u = 0; u < 4; u++) {
                rec[0] = __fadd_rn(rec[0], v[u].x);
                rec[1] = __fadd_rn(rec[1], v[u].y);
                rec[2] = __fadd_rn(rec[2], v[u].z);
                rec[3] = __fadd_rn(rec[3], v[u].w);
            }
        }
        for (; e < total; e++) {
            float4 wv = wt4[(size_t)list[p][e] * 128 + tid];
            rec[0] = __fadd_rn(rec[0], wv.x);
            rec[1] = __fadd_rn(rec[1], wv.y);
            rec[2] = __fadd_rn(rec[2], wv.z);
            rec[3] = __fadd_rn(rec[3], wv.w);
        }

        float ff[4] = {ffv.x, ffv.y, ffv.z, ffv.w};
#pragma unroll
        for (int k = 0; k < 4; k++) {
            float inp = __fadd_rn(__fadd_rn(ff[k], rec[k]), b2[k]);
            alif(inp, m[k], s[k], bb[k], alf[k], omA[k], ro[k], omR[k]);
        }
        ffv = ffn;
    }
#pragma unroll
    for (int k = 0; k < 4; k++) s3sm[tid * 4 + k] = s[k];
    __syncthreads();
    if (tid < 11) {
        float acc = 0.f;
        for (int j = 0; j < 512; j++)
            acc = __fmaf_rn(s3sm[j], w_h2o3[(size_t)tid * 512 + j], acc);
        out[n * 11 + tid] = __fadd_rn(acc, b_h2o3[tid]);
    }
}

// ---------------------------------------------------------------------------
extern "C" void kernel_launch(void* const* d_in, const int* in_sizes, int n_in,
                              void* d_out, int out_size) {
    const float* x          = (const float*)d_in[0];
    const float* w_i2h1     = (const float*)d_in[1];
    const float* b_i2h1     = (const float*)d_in[2];
    const float* w_i2h2     = (const float*)d_in[3];
    const float* b_i2h2     = (const float*)d_in[4];
    const float* w_i2h3     = (const float*)d_in[5];
    const float* b_i2h3     = (const float*)d_in[6];
    const float* w_h2h3     = (const float*)d_in[7];
    const float* b_h2h3     = (const float*)d_in[8];
    const float* w_h2o3     = (const float*)d_in[9];
    const float* b_h2o3     = (const float*)d_in[10];
    const float* tau_adp_h1 = (const float*)d_in[11];
    const float* tau_adp_h2 = (const float*)d_in[12];
    const float* tau_adp_h3 = (const float*)d_in[13];
    const float* tau_m_h1   = (const float*)d_in[14];
    const float* tau_m_h2   = (const float*)d_in[15];
    const float* tau_m_h3   = (const float*)d_in[16];
    float* out = (float*)d_out;

    float *xp, *in12, *s12, *ff3;
    cudaGetSymbolAddress((void**)&xp,   d_xp);
    cudaGetSymbolAddress((void**)&in12, d_in12);
    cudaGetSymbolAddress((void**)&s12,  d_s12);
    cudaGetSymbolAddress((void**)&ff3,  d_ff3);

    pool_tr_kernel<<<25856, 256>>>(x, w_h2h3);   // pool (2 out/thread) + transpose

    // merged GEMM1+2: grid (8 col-tiles, 50 row-tiles, 2 channels) = 800 CTAs
    gemm_nt<<<dim3(8, 50, 2), 256>>>(
        xp, xp + (size_t)T_STEPS * NBATCH * INSZ,
        w_i2h1, w_i2h2, b_i2h1, b_i2h2,
        in12, in12 + (size_t)T_STEPS * NBATCH * HID);

    scan12_kernel<<<128, 256>>>(tau_adp_h1, tau_adp_h2, tau_m_h1, tau_m_h2);

    // GEMM3: 400 CTAs
    gemm_nt<<<dim3(8, 50, 1), 256>>>(
        s12, s12, w_i2h3, w_i2h3, b_i2h3, b_i2h3, ff3, ff3);

    layer3_kernel<<<NBATCH, 128>>>(w_h2o3, b_h2o3, b_h2h3, tau_adp_h3, tau_m_h3, out);
}

// round 17
// speedup vs baseline: 1.1810x; 1.0030x over previous
#include <cuda_runtime.h>
#include <cuda_bf16.h>
#include <math.h>

// ---------------------------------------------------------------------------
// SRNN ALIF — bit-exact-vs-XLA-CPU fp32 (round 17).
// = round 16 (best, 756.0) with:
//   - layer3: 1 barrier/step via per-warp list segments (chains bit-identical)
//   - layer3: parallel output GEMV (final output only — reorder safe)
//   - pool: 4 outputs/thread (MLP 16)
// ---------------------------------------------------------------------------

#define T_STEPS 100
#define NBATCH  64
#define HID     512
#define INSZ    1024

__device__ float d_xp  [2 * T_STEPS * NBATCH * INSZ];   // pooled [c][t][n][1024]
__device__ float d_in12[2 * T_STEPS * NBATCH * HID];    // ff proj [c][t][n][512]
__device__ float d_s12 [T_STEPS * NBATCH * INSZ];       // spikes s1||s2 [t][n][1024]
__device__ float d_ff3 [T_STEPS * NBATCH * HID];        // concat@W1 (+b1) [t][n][512]
__device__ float d_wt  [HID * HID];                     // w_h2h3 transposed [j][i]

// ---------------------------------------------------------------------------
// XLA:CPU exp — Cephes/Eigen pexp<float> with FMA, exact op order.
// ---------------------------------------------------------------------------
__device__ __forceinline__ float xla_expf(float x) {
    const float exp_hi = 88.723164f, exp_lo = -88.723164f;
    x = fminf(fmaxf(x, exp_lo), exp_hi);
    float m = floorf(__fmaf_rn(x, 1.44269504088896341f, 0.5f));
    float r = __fmaf_rn(m, -0.693359375f, x);
    r = __fmaf_rn(m, 2.12194440e-4f, r);
    float r2 = __fmul_rn(r, r);
    float y = 1.9875691500e-4f;
    y = __fmaf_rn(y, r, 1.3981999507e-3f);
    y = __fmaf_rn(y, r, 8.3334519073e-3f);
    y = __fmaf_rn(y, r, 4.1665795894e-2f);
    y = __fmaf_rn(y, r, 1.6666665459e-1f);
    y = __fmaf_rn(y, r, 5.0000001201e-1f);
    y = __fmaf_rn(y, r2, r);
    y = __fadd_rn(y, 1.0f);
    return ldexpf(y, (int)m);
}

__device__ __forceinline__ float alpha_of(float tau) {
    return xla_expf(__fdiv_rn(-1.0f, tau));
}

// ---------------------------------------------------------------------------
// 1) maxpool 4x4 stride 4 (exact), 4 outputs/thread (MLP 16) + transpose of
//    w_h2h3 folded in. Blocks [0,12800): pool; [12800,13056): transpose.
// ---------------------------------------------------------------------------
__device__ __forceinline__ const float* pool_src(int out, const float* x) {
    int i    = out & 1023;
    int n    = (out >> 10) & 63;
    int rest = out >> 16;          // c*100 + t
    int t    = rest % 100;
    int c    = rest / 100;
    int ph = i >> 5, pw = i & 31;
    return x + (((size_t)(n * 100 + t) * 2 + c) << 14) + ph * 512 + pw * 4;
}

__global__ void pool_tr_kernel(const float* __restrict__ x,
                               const float* __restrict__ w) {
    if (blockIdx.x < 12800) {
        int outb = blockIdx.x * 1024 + threadIdx.x;
        const float* bsrc[4];
#pragma unroll
        for (int u = 0; u < 4; u++) bsrc[u] = pool_src(outb + 256 * u, x);
        float4 v[16];
#pragma unroll
        for (int u = 0; u < 4; u++)
#pragma unroll
            for (int r = 0; r < 4; r++)
                v[u * 4 + r] = *(const float4*)(bsrc[u] + r * 128);
        float mx[4];
#pragma unroll
        for (int u = 0; u < 4; u++) {
            float m0 = -3.4e38f;
#pragma unroll
            for (int r = 0; r < 4; r++) {
                float4 q = v[u * 4 + r];
                m0 = fmaxf(m0, fmaxf(fmaxf(q.x, q.y), fmaxf(q.z, q.w)));
            }
            mx[u] = m0;
        }
#pragma unroll
        for (int u = 0; u < 4; u++) d_xp[outb + 256 * u] = mx[u];
    } else {
        __shared__ float tile[32][33];
        int b  = blockIdx.x - 12800;       // 0..255
        int bx = (b & 15) * 32, by = (b >> 4) * 32;
        int tx = threadIdx.x & 31, ty = threadIdx.x >> 5;   // 32 x 8
#pragma unroll
        for (int r = 0; r < 4; r++)
            tile[ty + 8 * r][tx] = w[(size_t)(by + ty + 8 * r) * 512 + bx + tx];
        __syncthreads();
#pragma unroll
        for (int r = 0; r < 4; r++)
            d_wt[(size_t)(bx + ty + 8 * r) * 512 + by + tx] = tile[tx][ty + 8 * r];
    }
}

// ---------------------------------------------------------------------------
// 2) fp32 GEMM (NT), BM=128 BN=64 BK=16, 8x4 micro-tile, serial ascending-k
//    FFMA per output, ping-pong smem + register prefetch, peeled final iter.
// ---------------------------------------------------------------------------
#define BM 128
#define BN 64
#define BK 16

__device__ __forceinline__ void gemm_compute_tile(
    const float As[BK][BM], const float Ws[BK][BN],
    int ty, int tx, float acc[8][4]) {
#pragma unroll
    for (int k = 0; k < BK; k++) {
        float a[8], w[4];
#pragma unroll
        for (int r = 0; r < 8; r++) a[r] = As[k][ty * 8 + r];
#pragma unroll
        for (int cI = 0; cI < 4; cI++) w[cI] = Ws[k][tx * 4 + cI];
#pragma unroll
        for (int r = 0; r < 8; r++)
#pragma unroll
            for (int cI = 0; cI < 4; cI++)
                acc[r][cI] = __fmaf_rn(a[r], w[cI], acc[r][cI]);
    }
}

__global__ __launch_bounds__(256, 3)
void gemm_nt(const float* __restrict__ A0, const float* __restrict__ A1,
             const float* __restrict__ W0, const float* __restrict__ W1,
             const float* __restrict__ b0, const float* __restrict__ b1,
             float* __restrict__ C0, float* __restrict__ C1) {
    __shared__ float As[2][BK][BM];
    __shared__ float Ws[2][BK][BN];
    int ch = blockIdx.z;
    const float* A = ch ? A1 : A0;
    const float* W = ch ? W1 : W0;
    const float* bias_a = ch ? b1 : b0;
    float* C = ch ? C1 : C0;

    int tid = threadIdx.x;
    int rowBase = blockIdx.y * BM;
    int colBase = blockIdx.x * BN;
    int tx = tid & 15;
    int ty = tid >> 4;
    int mA0 = (tid * 2)     >> 2, kqA0 = (tid * 2)     & 3;
    int mA1 = (tid * 2 + 1) >> 2, kqA1 = (tid * 2 + 1) & 3;
    int nW  = tid >> 2,           kqW  = tid & 3;
    const float* Arow0 = A + (size_t)(rowBase + mA0) * 1024 + kqA0 * 4;
    const float* Arow1 = A + (size_t)(rowBase + mA1) * 1024 + kqA1 * 4;
    const float* Wrow  = W + (size_t)(colBase + nW)  * 1024 + kqW  * 4;

    float acc[8][4];
#pragma unroll
    for (int r = 0; r < 8; r++)
#pragma unroll
        for (int cI = 0; cI < 4; cI++) acc[r][cI] = 0.f;

    {
        float4 v0 = *(const float4*)Arow0;
        float4 v1 = *(const float4*)Arow1;
        float4 vw = *(const float4*)Wrow;
        As[0][kqA0 * 4 + 0][mA0] = v0.x; As[0][kqA0 * 4 + 1][mA0] = v0.y;
        As[0][kqA0 * 4 + 2][mA0] = v0.z; As[0][kqA0 * 4 + 3][mA0] = v0.w;
        As[0][kqA1 * 4 + 0][mA1] = v1.x; As[0][kqA1 * 4 + 1][mA1] = v1.y;
        As[0][kqA1 * 4 + 2][mA1] = v1.z; As[0][kqA1 * 4 + 3][mA1] = v1.w;
        Ws[0][kqW * 4 + 0][nW] = vw.x; Ws[0][kqW * 4 + 1][nW] = vw.y;
        Ws[0][kqW * 4 + 2][nW] = vw.z; Ws[0][kqW * 4 + 3][nW] = vw.w;
    }
    __syncthreads();

    for (int it = 0; it < 63; ++it) {
        int cur = it & 1, nb = 1 - cur;
        int koff = (it + 1) * BK;
        float4 v0 = *(const float4*)(Arow0 + koff);
        float4 v1 = *(const float4*)(Arow1 + koff);
        float4 vw = *(const float4*)(Wrow  + koff);

        gemm_compute_tile(As[cur], Ws[cur], ty, tx, acc);

        As[nb][kqA0 * 4 + 0][mA0] = v0.x; As[nb][kqA0 * 4 + 1][mA0] = v0.y;
        As[nb][kqA0 * 4 + 2][mA0] = v0.z; As[nb][kqA0 * 4 + 3][mA0] = v0.w;
        As[nb][kqA1 * 4 + 0][mA1] = v1.x; As[nb][kqA1 * 4 + 1][mA1] = v1.y;
        As[nb][kqA1 * 4 + 2][mA1] = v1.z; As[nb][kqA1 * 4 + 3][mA1] = v1.w;
        Ws[nb][kqW * 4 + 0][nW] = vw.x; Ws[nb][kqW * 4 + 1][nW] = vw.y;
        Ws[nb][kqW * 4 + 2][nW] = vw.z; Ws[nb][kqW * 4 + 3][nW] = vw.w;
        __syncthreads();
    }
    gemm_compute_tile(As[1], Ws[1], ty, tx, acc);

    float badd[4];
#pragma unroll
    for (int cI = 0; cI < 4; cI++)
        badd[cI] = bias_a ? bias_a[colBase + tx * 4 + cI] : 0.f;
#pragma unroll
    for (int r = 0; r < 8; r++) {
        size_t rowOff = (size_t)(rowBase + ty * 8 + r) * 512 + colBase + tx * 4;
#pragma unroll
        for (int cI = 0; cI < 4; cI++)
            C[rowOff + cI] = __fadd_rn(acc[r][cI], badd[cI]);
    }
}

// ---------------------------------------------------------------------------
// ALIF update: XLA HLO op-for-op — every op individually rounded, no FMA.
// ---------------------------------------------------------------------------
__device__ __forceinline__ void alif(float inp, float& m, float& s, float& bb,
                                     float alpha, float omAlpha, float ro, float omRo) {
    bb = __fadd_rn(__fmul_rn(ro, bb), __fmul_rn(omRo, s));
    float B = __fadd_rn(0.1f, __fmul_rn(1.8f, bb));
    float t1 = __fadd_rn(__fmul_rn(m, alpha), __fmul_rn(omAlpha, inp));
    m = __fsub_rn(t1, __fmul_rn(B, s));
    s = (__fsub_rn(m, B) > 0.f) ? 1.f : 0.f;
}

// ---------------------------------------------------------------------------
// 3) Layers 1 & 2 scans — BOTH layers per thread (2 chains, MLP 8),
//    depth-4 register rings (4 divides T=100 -> stays in registers).
// ---------------------------------------------------------------------------
__global__ void scan12_kernel(const float* __restrict__ tau_adp1, const float* __restrict__ tau_adp2,
                              const float* __restrict__ tau_m1,  const float* __restrict__ tau_m2) {
    int tid = blockIdx.x * blockDim.x + threadIdx.x;   // 32768
    int h = tid & 511;
    int n = tid >> 9;                                  // 0..63
    float alpha0 = alpha_of(tau_m1[h]),  ro0 = alpha_of(tau_adp1[h]);
    float alpha1 = alpha_of(tau_m2[h]),  ro1 = alpha_of(tau_adp2[h]);
    float omA0 = __fsub_rn(1.0f, alpha0), omR0 = __fsub_rn(1.0f, ro0);
    float omA1 = __fsub_rn(1.0f, alpha1), omR1 = __fsub_rn(1.0f, ro1);
    float m0 = 0.f, bb0 = 0.1f, s0 = 0.f;
    float m1 = 0.f, bb1 = 0.1f, s1 = 0.f;
    const float* in0 = d_in12 + (size_t)n * HID + h;
    const float* in1 = in0 + (size_t)T_STEPS * NBATCH * HID;
    float* sb = d_s12 + (size_t)n * INSZ + h;

    float buf0[4], buf1[4];
#pragma unroll
    for (int j = 0; j < 4; j++) {
        buf0[j] = in0[(size_t)j * NBATCH * HID];
        buf1[j] = in1[(size_t)j * NBATCH * HID];
    }
    for (int t = 0; t < T_STEPS; t++) {
        float i0 = buf0[t & 3], i1 = buf1[t & 3];
        if (t + 4 < T_STEPS) {
            buf0[t & 3] = in0[(size_t)(t + 4) * NBATCH * HID];
            buf1[t & 3] = in1[(size_t)(t + 4) * NBATCH * HID];
        }
        alif(i0, m0, s0, bb0, alpha0, omA0, ro0, omR0);
        alif(i1, m1, s1, bb1, alpha1, omA1, ro1, omR1);
        sb[(size_t)t * NBATCH * INSZ]       = s0;
        sb[(size_t)t * NBATCH * INSZ + HID] = s1;
    }
}

// ---------------------------------------------------------------------------
// 4) Layer-3 sequential scan. One CTA/batch, 128 threads x 4 neurons.
//    ONE barrier/step: actives written into per-warp segments (warp w owns
//    list[p][w*128 ..]); gather maps global ascending index e -> (segment,
//    offset). Global order stays ascending-j => FADD chains bit-identical.
//    ff3 ring prefetch; gather loads batched 16-wide.
// ---------------------------------------------------------------------------
__global__ __launch_bounds__(128)
void layer3_kernel(const float* __restrict__ w_h2o3, const float* __restrict__ b_h2o3,
                   const float* __restrict__ b_h2h3,
                   const float* __restrict__ tau_adp, const float* __restrict__ tau_m,
                   float* __restrict__ out) {
    int n = blockIdx.x;
    int tid = threadIdx.x;          // neurons 4*tid .. 4*tid+3
    int lane = tid & 31, wrp = tid >> 5;
    unsigned ltmask = (1u << lane) - 1u;
    __shared__ int   list[2][512];  // 4 segments of 128 per parity
    __shared__ int   wcnt[2][4];
    __shared__ float s3sm[512];

    float m[4], bb[4], s[4], alf[4], ro[4], omA[4], omR[4], b2[4];
#pragma unroll
    for (int k = 0; k < 4; k++) {
        int j = tid * 4 + k;
        alf[k] = alpha_of(tau_m[j]);
        ro[k]  = alpha_of(tau_adp[j]);
        omA[k] = __fsub_rn(1.0f, alf[k]);
        omR[k] = __fsub_rn(1.0f, ro[k]);
        b2[k]  = b_h2h3[j];          // zero in practice
        m[k] = 0.f; bb[k] = 0.1f; s[k] = 0.f;
    }
    const float4* wt4 = (const float4*)d_wt;   // [j][i/4] float4
    const float4* ff4 = (const float4*)d_ff3;  // [(t*64+n)*128 + tid]

    float4 ffv = ff4[(size_t)n * 128 + tid];   // t = 0

    for (int t = 0; t < T_STEPS; t++) {
        // prefetch next step's ff values — overlaps compaction + gather
        float4 ffn;
        if (t + 1 < T_STEPS) ffn = ff4[((size_t)(t + 1) * NBATCH + n) * 128 + tid];

        int p = t & 1;
        unsigned bal[4];
#pragma unroll
        for (int k = 0; k < 4; k++)
            bal[k] = __ballot_sync(0xffffffffu, s[k] != 0.f);
        int offw = 0, cntw = 0;
#pragma unroll
        for (int k = 0; k < 4; k++) {
            offw += __popc(bal[k] & ltmask);
            cntw += __popc(bal[k]);
        }
        if (lane == 0) wcnt[p][wrp] = cntw;
        int pos = wrp * 128 + offw;
#pragma unroll
        for (int k = 0; k < 4; k++)            // lane-major, k-minor -> ascending j
            if (s[k] != 0.f) list[p][pos++] = tid * 4 + k;
        __syncthreads();                       // single barrier per step

        int cw0 = wcnt[p][0], cw1 = wcnt[p][1], cw2 = wcnt[p][2], cw3 = wcnt[p][3];
        int st1 = cw0, st2 = cw0 + cw1, st3 = st2 + cw2;
        int total = st3 + cw3;

        // e -> segment address (global ascending j preserved)
        auto laddr = [&](int e) {
            int w = (e >= st1) + (e >= st2) + (e >= st3);
            int strt = (w == 0) ? 0 : ((w == 1) ? st1 : ((w == 2) ? st2 : st3));
            return w * 128 + (e - strt);
        };

        float rec[4] = {0.f, 0.f, 0.f, 0.f};
        int e = 0;
        for (; e + 16 <= total; e += 16) {
            float4 v[16];
#pragma unroll
            for (int u = 0; u < 16; u++)
                v[u] = wt4[(size_t)list[p][laddr(e + u)] * 128 + tid];
#pragma unroll
            for (int u = 0; u < 16; u++) {
                rec[0] = __fadd_rn(rec[0], v[u].x);
                rec[1] = __fadd_rn(rec[1], v[u].y);
                rec[2] = __fadd_rn(rec[2], v[u].z);
                rec[3] = __fadd_rn(rec[3], v[u].w);
            }
        }
        for (; e + 4 <= total; e += 4) {
            float4 v[4];
#pragma unroll
            for (int u = 0; u < 4; u++)
                v[u] = wt4[(size_t)list[p][laddr(e + u)] * 128 + tid];
#pragma unroll
            for (int u = 0; u < 4; u++) {
                rec[0] = __fadd_rn(rec[0], v[u].x);
                rec[1] = __fadd_rn(rec[1], v[u].y);
                rec[2] = __fadd_rn(rec[2], v[u].z);
                rec[3] = __fadd_rn(rec[3], v[u].w);
            }
        }
        for (; e < total; e++) {
            float4 wv = wt4[(size_t)list[p][laddr(e)] * 128 + tid];
            rec[0] = __fadd_rn(rec[0], wv.x);
            rec[1] = __fadd_rn(rec[1], wv.y);
            rec[2] = __fadd_rn(rec[2], wv.z);
            rec[3] = __fadd_rn(rec[3], wv.w);
        }

        float ff[4] = {ffv.x, ffv.y, ffv.z, ffv.w};
#pragma unroll
        for (int k = 0; k < 4; k++) {
            float inp = __fadd_rn(__fadd_rn(ff[k], rec[k]), b2[k]);
            alif(inp, m[k], s[k], bb[k], alf[k], omA[k], ro[k], omR[k]);
        }
        ffv = ffn;
    }
#pragma unroll
    for (int k = 0; k < 4; k++) s3sm[tid * 4 + k] = s[k];
    __syncthreads();

    // Output GEMV — final output only (1e-3 tolerance): warp-parallel reduce.
    for (int o = wrp; o < 11; o += 4) {
        float part = 0.f;
        for (int j = lane; j < 512; j += 32)
            part = __fmaf_rn(s3sm[j], w_h2o3[(size_t)o * 512 + j], part);
#pragma unroll
        for (int d = 16; d; d >>= 1)
            part = __fadd_rn(part, __shfl_xor_sync(0xffffffffu, part, d));
        if (lane == 0) out[n * 11 + o] = __fadd_rn(part, b_h2o3[o]);
    }
}

// ---------------------------------------------------------------------------
extern "C" void kernel_launch(void* const* d_in, const int* in_sizes, int n_in,
                              void* d_out, int out_size) {
    const float* x          = (const float*)d_in[0];
    const float* w_i2h1     = (const float*)d_in[1];
    const float* b_i2h1     = (const float*)d_in[2];
    const float* w_i2h2     = (const float*)d_in[3];
    const float* b_i2h2     = (const float*)d_in[4];
    const float* w_i2h3     = (const float*)d_in[5];
    const float* b_i2h3     = (const float*)d_in[6];
    const float* w_h2h3     = (const float*)d_in[7];
    const float* b_h2h3     = (const float*)d_in[8];
    const float* w_h2o3     = (const float*)d_in[9];
    const float* b_h2o3     = (const float*)d_in[10];
    const float* tau_adp_h1 = (const float*)d_in[11];
    const float* tau_adp_h2 = (const float*)d_in[12];
    const float* tau_adp_h3 = (const float*)d_in[13];
    const float* tau_m_h1   = (const float*)d_in[14];
    const float* tau_m_h2   = (const float*)d_in[15];
    const float* tau_m_h3   = (const float*)d_in[16];
    float* out = (float*)d_out;

    float *xp, *in12, *s12, *ff3;
    cudaGetSymbolAddress((void**)&xp,   d_xp);
    cudaGetSymbolAddress((void**)&in12, d_in12);
    cudaGetSymbolAddress((void**)&s12,  d_s12);
    cudaGetSymbolAddress((void**)&ff3,  d_ff3);

    pool_tr_kernel<<<13056, 256>>>(x, w_h2h3);   // pool (4 out/thread) + transpose

    // merged GEMM1+2: grid (8 col-tiles, 50 row-tiles, 2 channels) = 800 CTAs
    gemm_nt<<<dim3(8, 50, 2), 256>>>(
        xp, xp + (size_t)T_STEPS * NBATCH * INSZ,
        w_i2h1, w_i2h2, b_i2h1, b_i2h2,
        in12, in12 + (size_t)T_STEPS * NBATCH * HID);

    scan12_kernel<<<128, 256>>>(tau_adp_h1, tau_adp_h2, tau_m_h1, tau_m_h2);

    // GEMM3: 400 CTAs
    gemm_nt<<<dim3(8, 50, 1), 256>>>(
        s12, s12, w_i2h3, w_i2h3, b_i2h3, b_i2h3, ff3, ff3);

    layer3_kernel<<<NBATCH, 128>>>(w_h2o3, b_h2o3, b_h2h3, tau_adp_h3, tau_m_h3, out);
}